// round 2
// baseline (speedup 1.0000x reference)
#include <cuda_runtime.h>
#include <cstdint>

// out[r][c] = in[2r+1][2c+1], in: 8192x8192 f32, out: 4096x4096 f32.
//
// Each thread produces 4 output float4 (one vec position in 4 consecutive
// output rows). 8 input float4 loads are front-batched (MLP_p1=8), then 4
// coalesced float4 stores. Lane-contiguous addressing within every memory
// instruction (16 contiguous 32B sectors per warp request).
//
// Streaming cache hints (__ldcs/__stcs): data is single-use, keep L2 clean.

static constexpr int N_IN  = 8192;
static constexpr int N_OUT = 4096;
static constexpr int VECS_PER_ROW = N_OUT / 4;        // 1024 float4 per output row
static constexpr int IN_ROW_V4    = N_IN / 4;         // 2048 float4 per input row
static constexpr int ROWS_PER_THREAD = 4;

__global__ void __launch_bounds__(256)
downsample2x_kernel(const float4* __restrict__ in, float4* __restrict__ out) {
    unsigned tid = blockIdx.x * blockDim.x + threadIdx.x;  // 0 .. 1,048,575
    unsigned vec = tid & (VECS_PER_ROW - 1);               // 0..1023
    unsigned rg  = tid >> 10;                              // row group 0..1023

    // First input row of this group: 2*(4*rg) + 1 = 8*rg + 1.
    // Consecutive output rows -> input rows step by 2 (= 2*IN_ROW_V4 float4).
    const float4* p = in + (size_t)(8u * rg + 1u) * IN_ROW_V4 + 2u * vec;

    // Front-batched loads: 8 independent LDG.128 (streaming, evict-first).
    float4 a0 = __ldcs(p + 0 * 2 * IN_ROW_V4);
    float4 b0 = __ldcs(p + 0 * 2 * IN_ROW_V4 + 1);
    float4 a1 = __ldcs(p + 1 * 2 * IN_ROW_V4);
    float4 b1 = __ldcs(p + 1 * 2 * IN_ROW_V4 + 1);
    float4 a2 = __ldcs(p + 2 * 2 * IN_ROW_V4);
    float4 b2 = __ldcs(p + 2 * 2 * IN_ROW_V4 + 1);
    float4 a3 = __ldcs(p + 3 * 2 * IN_ROW_V4);
    float4 b3 = __ldcs(p + 3 * 2 * IN_ROW_V4 + 1);

    float4* q = out + (size_t)(4u * rg) * VECS_PER_ROW + vec;

    __stcs(q + 0 * VECS_PER_ROW, make_float4(a0.y, a0.w, b0.y, b0.w));
    __stcs(q + 1 * VECS_PER_ROW, make_float4(a1.y, a1.w, b1.y, b1.w));
    __stcs(q + 2 * VECS_PER_ROW, make_float4(a2.y, a2.w, b2.y, b2.w));
    __stcs(q + 3 * VECS_PER_ROW, make_float4(a3.y, a3.w, b3.y, b3.w));
}

extern "C" void kernel_launch(void* const* d_in, const int* in_sizes, int n_in,
                              void* d_out, int out_size) {
    const float4* in  = (const float4*)d_in[0];
    float4*       out = (float4*)d_out;

    const int total_threads = (N_OUT / ROWS_PER_THREAD) * VECS_PER_ROW; // 1,048,576
    const int block = 256;
    const int grid  = total_threads / block;                            // 4096

    downsample2x_kernel<<<grid, block>>>(in, out);
}